// round 10
// baseline (speedup 1.0000x reference)
#include <cuda_runtime.h>
#include <cuda_bf16.h>
#include <cstdint>
#include <cstddef>

#define BATCH 2
#define NTOK 2048
#define CDIM 1152
#define HEADS 16
#define HD 72
#define BH (BATCH*HEADS)      /* 32   */
#define MROWS (BATCH*NTOK)    /* 4096 */
#define K3 (3*CDIM)           /* 3456 */
#define QK_PAD 96
#define QK_SST 112
#define ATT_SCALE 0.11785113019775793f  /* 72^-0.5 */

#define GK CDIM
#define BK 64                 /* K per smem chunk (bf16 elems) */
#define CHPS (GK/BK)          /* 18 */
#define NCHUNK (3*CHPS)       /* 54 */
#define SMST 72               /* smem row stride in bf16 (144 B = 128 data + 16 skew) */
#define GS 4
#define GM 256                /* CTA tile rows */
#define GN 128                /* CTA tile cols */
#define ABUF (GM*SMST*2)      /* 36864 */
#define BBUF (GN*SMST*2)      /* 18432 */
#define STGB (ABUF+BBUF)      /* 55296 */
#define GEMM_SMEM (GS*STGB)   /* 221184 */

// ---------------- scratch (static device memory) ----------------
__device__ float g_qkv[(size_t)MROWS * K3];
__device__ __align__(16) signed char g_q8[(size_t)BH * NTOK * QK_PAD];
__device__ __align__(16) signed char g_k8[(size_t)BH * NTOK * QK_PAD];
__device__ float g_qs[BH * NTOK];
__device__ float g_ks[BH * NTOK];
__device__ __align__(16) signed char g_v8[(size_t)BH * HD * NTOK];   // [bh][d][m]
__device__ float g_vs[BH * HD];
__device__ int   g_vamax[BH * HD];
__device__ float g_logits[(size_t)BH * NTOK * NTOK];
__device__ __align__(16) unsigned char g_p8[(size_t)BH * NTOK * NTOK];
__device__ float g_rowfac[BH * NTOK];

// bf16 split operands
__device__ __align__(16) __nv_bfloat16 g_x_hi[(size_t)MROWS * CDIM];
__device__ __align__(16) __nv_bfloat16 g_x_lo[(size_t)MROWS * CDIM];
__device__ __align__(16) __nv_bfloat16 g_wq_hi[(size_t)K3 * CDIM];
__device__ __align__(16) __nv_bfloat16 g_wq_lo[(size_t)K3 * CDIM];
__device__ __align__(16) __nv_bfloat16 g_wp_hi[(size_t)CDIM * CDIM];
__device__ __align__(16) __nv_bfloat16 g_wp_lo[(size_t)CDIM * CDIM];
__device__ __align__(16) __nv_bfloat16 g_ctx_hi[(size_t)MROWS * CDIM];
__device__ __align__(16) __nv_bfloat16 g_ctx_lo[(size_t)MROWS * CDIM];

// ---------------- helpers ----------------
__device__ __forceinline__ uint32_t smem_u32(const void* p) {
    uint32_t a;
    asm("{ .reg .u64 t; cvta.to.shared.u64 t, %1; cvt.u32.u64 %0, t; }" : "=r"(a) : "l"(p));
    return a;
}
__device__ __forceinline__ uint32_t lds32(uint32_t addr) {
    uint32_t v;
    asm volatile("ld.shared.b32 %0, [%1];" : "=r"(v) : "r"(addr));
    return v;
}
__device__ __forceinline__ void mma_bf16(float* c, uint32_t a0, uint32_t a1,
                                         uint32_t a2, uint32_t a3,
                                         uint32_t b0, uint32_t b1) {
    asm volatile(
        "mma.sync.aligned.m16n8k16.row.col.f32.bf16.bf16.f32 "
        "{%0,%1,%2,%3}, {%4,%5,%6,%7}, {%8,%9}, {%0,%1,%2,%3};"
        : "+f"(c[0]), "+f"(c[1]), "+f"(c[2]), "+f"(c[3])
        : "r"(a0), "r"(a1), "r"(a2), "r"(a3), "r"(b0), "r"(b1));
}
__device__ __forceinline__ void mma_s8(int* c, uint32_t a0, uint32_t a1,
                                       uint32_t a2, uint32_t a3,
                                       uint32_t b0, uint32_t b1) {
    asm volatile(
        "mma.sync.aligned.m16n8k32.row.col.s32.s8.s8.s32 "
        "{%0,%1,%2,%3}, {%4,%5,%6,%7}, {%8,%9}, {%0,%1,%2,%3};"
        : "+r"(c[0]), "+r"(c[1]), "+r"(c[2]), "+r"(c[3])
        : "r"(a0), "r"(a1), "r"(a2), "r"(a3), "r"(b0), "r"(b1));
}
__device__ __forceinline__ void mma_u8s8(int* c, uint32_t a0, uint32_t a1,
                                         uint32_t a2, uint32_t a3,
                                         uint32_t b0, uint32_t b1) {
    asm volatile(
        "mma.sync.aligned.m16n8k32.row.col.s32.u8.s8.s32 "
        "{%0,%1,%2,%3}, {%4,%5,%6,%7}, {%8,%9}, {%0,%1,%2,%3};"
        : "+r"(c[0]), "+r"(c[1]), "+r"(c[2]), "+r"(c[3])
        : "r"(a0), "r"(a1), "r"(a2), "r"(a3), "r"(b0), "r"(b1));
}
__device__ __forceinline__ void ldsm4(uint32_t& r0, uint32_t& r1, uint32_t& r2,
                                      uint32_t& r3, uint32_t addr) {
    asm volatile("ldmatrix.sync.aligned.m8n8.x4.shared.b16 {%0,%1,%2,%3}, [%4];"
                 : "=r"(r0), "=r"(r1), "=r"(r2), "=r"(r3) : "r"(addr));
}
__device__ __forceinline__ void cp16(uint32_t dst, const void* src) {
    asm volatile("cp.async.cg.shared.global [%0], [%1], 16;" :: "r"(dst), "l"(src));
}

// ---------------- split fp32 -> bf16 hi + lo ----------------
__global__ __launch_bounds__(256) void split_kernel(const float* __restrict__ s,
                                                    __nv_bfloat16* __restrict__ hi,
                                                    __nv_bfloat16* __restrict__ lo, int n)
{
    int i = blockIdx.x * 256 + threadIdx.x;
    if (i < n) {
        float v = s[i];
        __nv_bfloat16 h = __float2bfloat16_rn(v);
        hi[i] = h;
        lo[i] = __float2bfloat16_rn(v - __bfloat162float(h));
    }
}

// ---------------- HMMA bf16x3 GEMM: 256x128 CTA tile, BK=64, 512 threads ----------------
__global__ __launch_bounds__(512, 1) void hmma_gemm_bf16x3(
    const __nv_bfloat16* __restrict__ Ah, const __nv_bfloat16* __restrict__ Al,
    const __nv_bfloat16* __restrict__ Bh, const __nv_bfloat16* __restrict__ Bl,
    const float* __restrict__ bias, float* __restrict__ C, int ldc)
{
    extern __shared__ char dynsm[];

    const int tid = threadIdx.x;
    const int wid = tid >> 5;
    const int lane = tid & 31;
    const int g  = lane >> 2;
    const int tg = lane & 3;
    const int wm = wid >> 2;              // 0..3 -> 64-row slab
    const int wn = wid & 3;               // 0..3 -> 32-col slab
    const int m0 = blockIdx.y * GM;
    const int n0 = blockIdx.x * GN;

    const uint32_t s0 = smem_u32(dynsm);

    const int lq = lane >> 3, lr = lane & 7;
    const uint32_t a_off = (uint32_t)((wm * 64 + (lq & 1) * 8 + lr) * (SMST * 2) + (lq >> 1) * 16);
    const uint32_t b_off = (uint32_t)((wn * 32 + (lq >> 1) * 8 + lr) * (SMST * 2) + (lq & 1) * 16);

    float acc[4][4][4];
#pragma unroll
    for (int i = 0; i < 4; i++)
#pragma unroll
        for (int j = 0; j < 4; j++)
#pragma unroll
            for (int q = 0; q < 4; q++) acc[i][j][q] = 0.f;

    // per chunk: A 256 rows x 8 units of 16B, B 128 rows x 8 units -> 3072 cp16 / 512 thr = 6
    auto issue_loads = [&](int c, int stg) {
        int s = c / CHPS, kc = (c - s * CHPS) * BK;
        const __nv_bfloat16* Ag = (s == 1) ? Al : Ah;
        const __nv_bfloat16* Bg = (s == 2) ? Bl : Bh;
        uint32_t base = s0 + (uint32_t)stg * STGB;
#pragma unroll
        for (int i = 0; i < 6; i++) {
            int idx = i * 512 + tid;           // 0..3071
            int r = idx >> 3, u = idx & 7;     // 8 x 16B per row
            if (r < GM)
                cp16(base + (uint32_t)(r * (SMST * 2) + u * 16),
                     (const char*)(Ag + (size_t)(m0 + r) * GK + kc) + u * 16);
            else
                cp16(base + ABUF + (uint32_t)((r - GM) * (SMST * 2) + u * 16),
                     (const char*)(Bg + (size_t)(n0 + r - GM) * GK + kc) + u * 16);
        }
    };

#pragma unroll
    for (int s = 0; s < GS - 1; s++) {
        issue_loads(s, s);
        asm volatile("cp.async.commit_group;" ::: "memory");
    }

    for (int c = 0; c < NCHUNK; c++) {
        asm volatile("cp.async.wait_group %0;" :: "n"(GS - 2) : "memory");
        __syncthreads();
        if (c + GS - 1 < NCHUNK) issue_loads(c + GS - 1, (c + GS - 1) % GS);
        asm volatile("cp.async.commit_group;" ::: "memory");

        const uint32_t base = s0 + (uint32_t)(c % GS) * STGB;
        const uint32_t aB = base + a_off;
        const uint32_t bB = base + ABUF + b_off;
#pragma unroll
        for (int kk = 0; kk < 4; kk++) {
            uint32_t bf[4][2];
#pragma unroll
            for (int jj = 0; jj < 2; jj++) {
                uint32_t t0, t1, t2, t3;
                ldsm4(t0, t1, t2, t3, bB + (uint32_t)(jj * 16 * (SMST * 2) + kk * 32));
                bf[2 * jj][0] = t0;     bf[2 * jj][1] = t1;
                bf[2 * jj + 1][0] = t2; bf[2 * jj + 1][1] = t3;
            }
#pragma unroll
            for (int i = 0; i < 4; i++) {
                uint32_t a0, a1, a2, a3;
                ldsm4(a0, a1, a2, a3, aB + (uint32_t)(i * 16 * (SMST * 2) + kk * 32));
#pragma unroll
                for (int j = 0; j < 4; j++)
                    mma_bf16(acc[i][j], a0, a1, a2, a3, bf[j][0], bf[j][1]);
            }
        }
    }

#pragma unroll
    for (int i = 0; i < 4; i++) {
        int r0 = m0 + wm * 64 + i * 16 + g;
#pragma unroll
        for (int j = 0; j < 4; j++) {
            int cc = n0 + wn * 32 + j * 8 + tg * 2;
            float bx = 0.f, by = 0.f;
            if (bias) { bx = bias[cc]; by = bias[cc + 1]; }
            float2 v0 = { acc[i][j][0] + bx, acc[i][j][1] + by };
            float2 v1 = { acc[i][j][2] + bx, acc[i][j][3] + by };
            *(float2*)(C + (size_t)r0 * ldc + cc)       = v0;
            *(float2*)(C + (size_t)(r0 + 8) * ldc + cc) = v1;
        }
    }
}

// ---------------- per-row symmetric int8 quant of q and k ----------------
__global__ __launch_bounds__(256) void quant_qk_kernel()
{
    int warp = threadIdx.x >> 5, lane = threadIdx.x & 31;
    int row = blockIdx.x * 8 + warp;
    int t  = row >> 16;
    int rr = row & 65535;
    int bh = rr >> 11;
    int n  = rr & 2047;
    int b = bh >> 4, h = bh & 15;
    const float* src = g_qkv + (size_t)(b * NTOK + n) * K3 + t * CDIM + h * HD;

    float x0 = src[lane];
    float x1 = src[lane + 32];
    float x2 = (lane < 8) ? src[lane + 64] : 0.f;
    float amax = fmaxf(fabsf(x0), fmaxf(fabsf(x1), fabsf(x2)));
#pragma unroll
    for (int s = 16; s; s >>= 1) amax = fmaxf(amax, __shfl_xor_sync(0xffffffffu, amax, s));
    float scale = fmaxf(amax, 1e-8f) / 127.0f;

    signed char* dst = (t ? g_k8 : g_q8) + (size_t)(bh * NTOK + n) * QK_PAD;
    int q0 = min(127, max(-128, (int)rintf(__fdiv_rn(x0, scale))));
    int q1 = min(127, max(-128, (int)rintf(__fdiv_rn(x1, scale))));
    dst[lane]      = (signed char)q0;
    dst[lane + 32] = (signed char)q1;
    if (lane < 8) {
        int q2 = min(127, max(-128, (int)rintf(__fdiv_rn(x2, scale))));
        dst[lane + 64] = (signed char)q2;
    } else {
        dst[lane + 64] = 0;
    }
    if (lane == 0) (t ? g_ks : g_qs)[bh * NTOK + n] = scale;
}

// ---------------- v quant: clear / amax / quantize+transpose ----------------
__global__ __launch_bounds__(256) void vamax_clear_kernel()
{
    int i = blockIdx.x * 256 + threadIdx.x;
    if (i < BH * HD) g_vamax[i] = 0;
}

__global__ __launch_bounds__(256) void vamax_kernel()
{
    int bh = blockIdx.y, chunk = blockIdx.x;
    int b = bh >> 4, h = bh & 15;
    __shared__ int sm[HD];
    if (threadIdx.x < HD) sm[threadIdx.x] = 0;
    __syncthreads();

    const float* base = g_qkv + (size_t)b * NTOK * K3 + 2 * CDIM + h * HD;
    for (int idx = threadIdx.x; idx < 256 * HD; idx += 256) {
        int n = chunk * 256 + idx / HD;
        int d = idx % HD;
        float v = fabsf(base[(size_t)n * K3 + d]);
        atomicMax(&sm[d], __float_as_int(v));
    }
    __syncthreads();
    if (threadIdx.x < HD)
        atomicMax(&g_vamax[bh * HD + threadIdx.x], sm[threadIdx.x]);
}

#define VQ_SST 264
__global__ __launch_bounds__(256) void vquant_kernel()
{
    int bh = blockIdx.y, chunk = blockIdx.x;
    int b = bh >> 4, h = bh & 15;
    __shared__ char tile[HD * VQ_SST];
    __shared__ float scS[HD];
    if (threadIdx.x < HD) {
        float amax = __int_as_float(g_vamax[bh * HD + threadIdx.x]);
        float sc = fmaxf(amax, 1e-8f) / 127.0f;
        scS[threadIdx.x] = sc;
        if (chunk == 0) g_vs[bh * HD + threadIdx.x] = sc;
    }
    __syncthreads();

    const float* base = g_qkv + (size_t)b * NTOK * K3 + 2 * CDIM + h * HD;
    for (int idx = threadIdx.x; idx < 256 * HD; idx += 256) {
        int nl = idx / HD;
        int d  = idx % HD;
        float v = base[(size_t)(chunk * 256 + nl) * K3 + d];
        int q = min(127, max(-128, (int)rintf(__fdiv_rn(v, scS[d]))));
        tile[d * VQ_SST + nl] = (char)q;
    }
    __syncthreads();

    for (int idx = threadIdx.x; idx < HD * 64; idx += 256) {
        int d = idx >> 6, w = idx & 63;
        int val = *(const int*)&tile[d * VQ_SST + w * 4];
        *(int*)(g_v8 + (size_t)(bh * HD + d) * NTOK + chunk * 256 + w * 4) = val;
    }
}

// ---------------- int8 QK^T logits GEMM (IMMA m16n8k32), 128x128 tile ----------------
__global__ __launch_bounds__(256) void logits_kernel()
{
    int bh   = blockIdx.z;
    int row0 = blockIdx.y * 128;
    int col0 = blockIdx.x * 128;
    __shared__ char qS[128 * QK_SST];
    __shared__ char kS[128 * QK_SST];

    const int tid = threadIdx.x;
    const char* qg = (const char*)(g_q8 + (size_t)(bh * NTOK + row0) * QK_PAD);
    const char* kg = (const char*)(g_k8 + (size_t)(bh * NTOK + col0) * QK_PAD);
#pragma unroll
    for (int it = 0; it < 3; it++) {
        int idx = tid + it * 256;
        int rr = idx / 6, u = idx % 6;
        *(uint4*)(qS + rr * QK_SST + u * 16) = *(const uint4*)(qg + rr * QK_PAD + u * 16);
        *(uint4*)(kS + rr * QK_SST + u * 16) = *(const uint4*)(kg + rr * QK_PAD + u * 16);
    }
    __syncthreads();

    const int wid = tid >> 5, lane = tid & 31;
    const int lg = lane >> 2, lt = lane & 3;
    const int wm = wid >> 2, wn = wid & 3;

    const uint32_t sq = smem_u32(qS);
    const uint32_t sk = smem_u32(kS);
    const uint32_t aBase = sq + (uint32_t)((wm * 64 + lg) * QK_SST + lt * 4);
    const uint32_t bBase = sk + (uint32_t)((wn * 32 + lg) * QK_SST + lt * 4);

    int acc[4][4][4] = {};
#pragma unroll
    for (int k = 0; k < 3; k++) {
        uint32_t bf[4][2];
#pragma unroll
        for (int j = 0; j < 4; j++) {
            uint32_t ba = bBase + (uint32_t)(j * 8 * QK_SST + k * 32);
            bf[j][0] = lds32(ba);
            bf[j][1] = lds32(ba + 16);
        }
#pragma unroll
        for (int i = 0; i < 4; i++) {
            uint32_t aa = aBase + (uint32_t)(i * 16 * QK_SST + k * 32);
            uint32_t a0 = lds32(aa);
            uint32_t a1 = lds32(aa + 8 * QK_SST);
            uint32_t a2 = lds32(aa + 16);
            uint32_t a3 = lds32(aa + 8 * QK_SST + 16);
#pragma unroll
            for (int j = 0; j < 4; j++)
                mma_s8(acc[i][j], a0, a1, a2, a3, bf[j][0], bf[j][1]);
        }
    }

#pragma unroll
    for (int i = 0; i < 4; i++) {
        int r0 = row0 + wm * 64 + i * 16 + lg;
        float qs0 = g_qs[bh * NTOK + r0] * ATT_SCALE;
        float qs1 = g_qs[bh * NTOK + r0 + 8] * ATT_SCALE;
#pragma unroll
        for (int j = 0; j < 4; j++) {
            int cc = col0 + wn * 32 + j * 8 + lt * 2;
            float2 kk = *(const float2*)&g_ks[bh * NTOK + cc];
            float2 v0 = { (float)acc[i][j][0] * qs0 * kk.x, (float)acc[i][j][1] * qs0 * kk.y };
            float2 v1 = { (float)acc[i][j][2] * qs1 * kk.x, (float)acc[i][j][3] * qs1 * kk.y };
            *(float2*)(g_logits + ((size_t)bh * NTOK + r0) * NTOK + cc)       = v0;
            *(float2*)(g_logits + ((size_t)bh * NTOK + r0 + 8) * NTOK + cc)   = v1;
        }
    }
}

// ---------------- softmax + unsigned 8-bit quant per row (512 thr, __expf) ----------------
__global__ __launch_bounds__(512) void softmax_kernel()
{
    size_t rowbase = (size_t)blockIdx.x * NTOK;
    const float* lrow = g_logits + rowbase;
    int tid = threadIdx.x;

    float4 l = *(const float4*)(lrow + tid * 4);
    float m = fmaxf(fmaxf(l.x, l.y), fmaxf(l.z, l.w));
    __shared__ float red[512];
    red[tid] = m;
    __syncthreads();
    for (int s = 256; s >= 1; s >>= 1) {
        if (tid < s) red[tid] = fmaxf(red[tid], red[tid + s]);
        __syncthreads();
    }
    m = red[0];
    __syncthreads();

    float e0 = __expf(l.x - m);
    float e1 = __expf(l.y - m);
    float e2 = __expf(l.z - m);
    float e3 = __expf(l.w - m);
    red[tid] = (e0 + e1) + (e2 + e3);
    __syncthreads();
    for (int s = 256; s >= 1; s >>= 1) {
        if (tid < s) red[tid] += red[tid + s];
        __syncthreads();
    }
    float z = red[0];

    int p0 = min(255, max(0, (int)rintf(255.0f * e0)));
    int p1 = min(255, max(0, (int)rintf(255.0f * e1)));
    int p2 = min(255, max(0, (int)rintf(255.0f * e2)));
    int p3 = min(255, max(0, (int)rintf(255.0f * e3)));
    unsigned packed = (unsigned)p0 | ((unsigned)p1 << 8) | ((unsigned)p2 << 16) | ((unsigned)p3 << 24);
    *(unsigned*)(g_p8 + rowbase + tid * 4) = packed;
    if (tid == 0) g_rowfac[blockIdx.x] = __fdiv_rn(1.0f, z) / 255.0f;
}

// ---------------- PV GEMM (IMMA u8.s8): ctx in split bf16 ----------------
#define PV_SST 48
__global__ __launch_bounds__(256, 2) void pv_kernel()
{
    int bh = blockIdx.y;
    int b = bh >> 4, h = bh & 15;
    int row0 = blockIdx.x * 256;

    __shared__ char pS[2][256 * PV_SST];
    __shared__ char vS[2][72 * PV_SST];

    const char* pg = (const char*)(g_p8 + ((size_t)bh * NTOK + row0) * NTOK);
    const char* vg = (const char*)(g_v8 + (size_t)bh * HD * NTOK);

    const int tid = threadIdx.x;
    const int wid = tid >> 5, lane = tid & 31;
    const int lg = lane >> 2, lt = lane & 3;
    const uint32_t sp0 = smem_u32(pS);
    const uint32_t sv0 = smem_u32(vS);

    auto issue = [&](int kc, int buf) {
        const char* srcp = pg + (size_t)tid * NTOK + kc * 32;
        uint32_t dstp = sp0 + (uint32_t)(buf * 256 * PV_SST + tid * PV_SST);
        cp16(dstp, srcp);
        cp16(dstp + 16, srcp + 16);
        if (tid < 144) {
            int rr = tid >> 1, u = tid & 1;
            cp16(sv0 + (uint32_t)(buf * 72 * PV_SST + rr * PV_SST + u * 16),
                 vg + (size_t)rr * NTOK + kc * 32 + u * 16);
        }
    };

    int acc[2][9][4] = {};

    issue(0, 0);
    asm volatile("cp.async.commit_group;" ::: "memory");

    for (int kc = 0; kc < 64; kc++) {
        const int buf = kc & 1;
        if (kc + 1 < 64) issue(kc + 1, buf ^ 1);
        asm volatile("cp.async.commit_group;" ::: "memory");
        asm volatile("cp.async.wait_group 1;" ::: "memory");
        __syncthreads();

        const uint32_t ap = sp0 + (uint32_t)(buf * 256 * PV_SST + (wid * 32 + lg) * PV_SST + lt * 4);
        const uint32_t bp = sv0 + (uint32_t)(buf * 72 * PV_SST + lg * PV_SST + lt * 4);

        uint32_t bf[9][2];
#pragma unroll
        for (int j = 0; j < 9; j++) {
            uint32_t ba = bp + (uint32_t)(j * 8 * PV_SST);
            bf[j][0] = lds32(ba);
            bf[j][1] = lds32(ba + 16);
        }
#pragma unroll
        for (int i = 0; i < 2; i++) {
            uint32_t aa = ap + (uint32_t)(i * 16 * PV_SST);
            uint32_t a0 = lds32(aa);
            uint32_t a1 = lds32(aa + 8 * PV_SST);
            uint32_t a2 = lds32(aa + 16);
            uint32_t a3 = lds32(aa + 8 * PV_SST + 16);
#pragma unroll
            for (int j = 0; j < 9; j++)
                mma_u8s8(acc[i][j], a0, a1, a2, a3, bf[j][0], bf[j][1]);
        }
        __syncthreads();
    }

#pragma unroll
    for (int i = 0; i < 2; i++) {
        int n0 = row0 + wid * 32 + i * 16 + lg;
        float rf0 = g_rowfac[bh * NTOK + n0];
        float rf1 = g_rowfac[bh * NTOK + n0 + 8];
#pragma unroll
        for (int j = 0; j < 9; j++) {
            int d = j * 8 + lt * 2;
            float vs0 = g_vs[bh * HD + d];
            float vs1 = g_vs[bh * HD + d + 1];
            float v00 = (float)acc[i][j][0] * rf0 * vs0;
            float v01 = (float)acc[i][j][1] * rf0 * vs1;
            float v10 = (float)acc[i][j][2] * rf1 * vs0;
            float v11 = (float)acc[i][j][3] * rf1 * vs1;
            size_t i0 = (size_t)(b * NTOK + n0) * CDIM + h * HD + d;
            size_t i1 = (size_t)(b * NTOK + n0 + 8) * CDIM + h * HD + d;
            __nv_bfloat16 h00 = __float2bfloat16_rn(v00);
            __nv_bfloat16 h01 = __float2bfloat16_rn(v01);
            __nv_bfloat16 h10 = __float2bfloat16_rn(v10);
            __nv_bfloat16 h11 = __float2bfloat16_rn(v11);
            *(__nv_bfloat162*)&g_ctx_hi[i0] = __nv_bfloat162(h00, h01);
            *(__nv_bfloat162*)&g_ctx_hi[i1] = __nv_bfloat162(h10, h11);
            *(__nv_bfloat162*)&g_ctx_lo[i0] = __nv_bfloat162(
                __float2bfloat16_rn(v00 - __bfloat162float(h00)),
                __float2bfloat16_rn(v01 - __bfloat162float(h01)));
            *(__nv_bfloat162*)&g_ctx_lo[i1] = __nv_bfloat162(
                __float2bfloat16_rn(v10 - __bfloat162float(h10)),
                __float2bfloat16_rn(v11 - __bfloat162float(h11)));
        }
    }
}

// ---------------- launch ----------------
extern "C" void kernel_launch(void* const* d_in, const int* in_sizes, int n_in,
                              void* d_out, int out_size)
{
    const float* x      = (const float*)d_in[0];
    const float* w_qkv  = (const float*)d_in[1];
    const float* w_proj = (const float*)d_in[2];
    const float* b_proj = (const float*)d_in[3];
    float* out = (float*)d_out;
    (void)in_sizes; (void)n_in; (void)out_size;

    void *p_qkv = nullptr;
    void *p_xh = nullptr, *p_xl = nullptr, *p_wqh = nullptr, *p_wql = nullptr;
    void *p_wph = nullptr, *p_wpl = nullptr, *p_cxh = nullptr, *p_cxl = nullptr;
    cudaGetSymbolAddress(&p_qkv, g_qkv);
    cudaGetSymbolAddress(&p_xh, g_x_hi);   cudaGetSymbolAddress(&p_xl, g_x_lo);
    cudaGetSymbolAddress(&p_wqh, g_wq_hi); cudaGetSymbolAddress(&p_wql, g_wq_lo);
    cudaGetSymbolAddress(&p_wph, g_wp_hi); cudaGetSymbolAddress(&p_wpl, g_wp_lo);
    cudaGetSymbolAddress(&p_cxh, g_ctx_hi); cudaGetSymbolAddress(&p_cxl, g_ctx_lo);

    cudaFuncSetAttribute(hmma_gemm_bf16x3, cudaFuncAttributeMaxDynamicSharedMemorySize, GEMM_SMEM);

    // 0) split fp32 operands into bf16 hi/lo
    {
        int nx = MROWS * CDIM, nq = K3 * CDIM, np = CDIM * CDIM;
        split_kernel<<<(nx + 255) / 256, 256>>>(x, (__nv_bfloat16*)p_xh, (__nv_bfloat16*)p_xl, nx);
        split_kernel<<<(nq + 255) / 256, 256>>>(w_qkv, (__nv_bfloat16*)p_wqh, (__nv_bfloat16*)p_wql, nq);
        split_kernel<<<(np + 255) / 256, 256>>>(w_proj, (__nv_bfloat16*)p_wph, (__nv_bfloat16*)p_wpl, np);
    }

    // 1) QKV projection (HMMA bf16x3), 256x128 tiles, BK=64
    hmma_gemm_bf16x3<<<dim3(K3 / GN, MROWS / GM), 512, GEMM_SMEM>>>(
        (const __nv_bfloat16*)p_xh, (const __nv_bfloat16*)p_xl,
        (const __nv_bfloat16*)p_wqh, (const __nv_bfloat16*)p_wql,
        nullptr, (float*)p_qkv, K3);

    // 2) quantize q,k per row; v per channel
    quant_qk_kernel<<<2 * BH * NTOK / 8, 256>>>();
    vamax_clear_kernel<<<(BH * HD + 255) / 256, 256>>>();
    vamax_kernel<<<dim3(NTOK / 256, BH), 256>>>();
    vquant_kernel<<<dim3(NTOK / 256, BH), 256>>>();

    // 3) int8 logits GEMM (IMMA)
    logits_kernel<<<dim3(NTOK / 128, NTOK / 128, BH), 256>>>();

    // 4) softmax + u8 quant
    softmax_kernel<<<BH * NTOK, 512>>>();

    // 5) PV GEMM (IMMA) -> ctx (split bf16)
    pv_kernel<<<dim3(NTOK / 256, BH), 256>>>();

    // 6) output projection + bias (HMMA bf16x3)
    hmma_gemm_bf16x3<<<dim3(CDIM / GN, MROWS / GM), 512, GEMM_SMEM>>>(
        (const __nv_bfloat16*)p_cxh, (const __nv_bfloat16*)p_cxl,
        (const __nv_bfloat16*)p_wph, (const __nv_bfloat16*)p_wpl,
        b_proj, out, CDIM);
}

// round 11
// speedup vs baseline: 1.0756x; 1.0756x over previous
#include <cuda_runtime.h>
#include <cuda_bf16.h>
#include <cstdint>
#include <cstddef>

#define BATCH 2
#define NTOK 2048
#define CDIM 1152
#define HEADS 16
#define HD 72
#define BH (BATCH*HEADS)      /* 32   */
#define MROWS (BATCH*NTOK)    /* 4096 */
#define K3 (3*CDIM)           /* 3456 */
#define QK_PAD 96
#define QK_SST 112
#define ATT_SCALE 0.11785113019775793f  /* 72^-0.5 */

#define GK CDIM
#define BK 128                /* K per smem chunk (bf16 elems) */
#define CHPS (GK/BK)          /* 9 */
#define NCHUNK (3*CHPS)       /* 27 */
#define SMST 136              /* smem row stride in bf16 (272 B = 256 data + 16 skew) */
#define GM 256                /* CTA tile rows */
#define GN 128                /* CTA tile cols */
#define ABUF (GM*SMST*2)      /* 69632 */
#define BBUF (GN*SMST*2)      /* 34816 */
#define STGB (ABUF+BBUF)      /* 104448 */
#define GEMM_SMEM (2*STGB)    /* 208896 */

// ---------------- scratch (static device memory) ----------------
__device__ float g_qkv[(size_t)MROWS * K3];
__device__ __align__(16) signed char g_q8[(size_t)BH * NTOK * QK_PAD];
__device__ __align__(16) signed char g_k8[(size_t)BH * NTOK * QK_PAD];
__device__ float g_qs[BH * NTOK];
__device__ float g_ks[BH * NTOK];
__device__ __align__(16) signed char g_v8[(size_t)BH * HD * NTOK];   // [bh][d][m]
__device__ float g_vs[BH * HD];
__device__ int   g_vamax[BH * HD];
__device__ float g_logits[(size_t)BH * NTOK * NTOK];
__device__ __align__(16) unsigned char g_p8[(size_t)BH * NTOK * NTOK];
__device__ float g_rowfac[BH * NTOK];

// bf16 split operands
__device__ __align__(16) __nv_bfloat16 g_x_hi[(size_t)MROWS * CDIM];
__device__ __align__(16) __nv_bfloat16 g_x_lo[(size_t)MROWS * CDIM];
__device__ __align__(16) __nv_bfloat16 g_wq_hi[(size_t)K3 * CDIM];
__device__ __align__(16) __nv_bfloat16 g_wq_lo[(size_t)K3 * CDIM];
__device__ __align__(16) __nv_bfloat16 g_wp_hi[(size_t)CDIM * CDIM];
__device__ __align__(16) __nv_bfloat16 g_wp_lo[(size_t)CDIM * CDIM];
__device__ __align__(16) __nv_bfloat16 g_ctx_hi[(size_t)MROWS * CDIM];
__device__ __align__(16) __nv_bfloat16 g_ctx_lo[(size_t)MROWS * CDIM];

// ---------------- helpers ----------------
__device__ __forceinline__ uint32_t smem_u32(const void* p) {
    uint32_t a;
    asm("{ .reg .u64 t; cvta.to.shared.u64 t, %1; cvt.u32.u64 %0, t; }" : "=r"(a) : "l"(p));
    return a;
}
__device__ __forceinline__ uint32_t lds32(uint32_t addr) {
    uint32_t v;
    asm volatile("ld.shared.b32 %0, [%1];" : "=r"(v) : "r"(addr));
    return v;
}
__device__ __forceinline__ void mma_bf16(float* c, uint32_t a0, uint32_t a1,
                                         uint32_t a2, uint32_t a3,
                                         uint32_t b0, uint32_t b1) {
    asm volatile(
        "mma.sync.aligned.m16n8k16.row.col.f32.bf16.bf16.f32 "
        "{%0,%1,%2,%3}, {%4,%5,%6,%7}, {%8,%9}, {%0,%1,%2,%3};"
        : "+f"(c[0]), "+f"(c[1]), "+f"(c[2]), "+f"(c[3])
        : "r"(a0), "r"(a1), "r"(a2), "r"(a3), "r"(b0), "r"(b1));
}
__device__ __forceinline__ void mma_s8(int* c, uint32_t a0, uint32_t a1,
                                       uint32_t a2, uint32_t a3,
                                       uint32_t b0, uint32_t b1) {
    asm volatile(
        "mma.sync.aligned.m16n8k32.row.col.s32.s8.s8.s32 "
        "{%0,%1,%2,%3}, {%4,%5,%6,%7}, {%8,%9}, {%0,%1,%2,%3};"
        : "+r"(c[0]), "+r"(c[1]), "+r"(c[2]), "+r"(c[3])
        : "r"(a0), "r"(a1), "r"(a2), "r"(a3), "r"(b0), "r"(b1));
}
__device__ __forceinline__ void mma_u8s8(int* c, uint32_t a0, uint32_t a1,
                                         uint32_t a2, uint32_t a3,
                                         uint32_t b0, uint32_t b1) {
    asm volatile(
        "mma.sync.aligned.m16n8k32.row.col.s32.u8.s8.s32 "
        "{%0,%1,%2,%3}, {%4,%5,%6,%7}, {%8,%9}, {%0,%1,%2,%3};"
        : "+r"(c[0]), "+r"(c[1]), "+r"(c[2]), "+r"(c[3])
        : "r"(a0), "r"(a1), "r"(a2), "r"(a3), "r"(b0), "r"(b1));
}
__device__ __forceinline__ void ldsm4(uint32_t& r0, uint32_t& r1, uint32_t& r2,
                                      uint32_t& r3, uint32_t addr) {
    asm volatile("ldmatrix.sync.aligned.m8n8.x4.shared.b16 {%0,%1,%2,%3}, [%4];"
                 : "=r"(r0), "=r"(r1), "=r"(r2), "=r"(r3) : "r"(addr));
}
__device__ __forceinline__ void cp16(uint32_t dst, const void* src) {
    asm volatile("cp.async.cg.shared.global [%0], [%1], 16;" :: "r"(dst), "l"(src));
}

// ---------------- split fp32 -> bf16 hi + lo ----------------
__global__ __launch_bounds__(256) void split_kernel(const float* __restrict__ s,
                                                    __nv_bfloat16* __restrict__ hi,
                                                    __nv_bfloat16* __restrict__ lo, int n)
{
    int i = blockIdx.x * 256 + threadIdx.x;
    if (i < n) {
        float v = s[i];
        __nv_bfloat16 h = __float2bfloat16_rn(v);
        hi[i] = h;
        lo[i] = __float2bfloat16_rn(v - __bfloat162float(h));
    }
}

// ---------------- HMMA bf16x3 GEMM: 256x128 CTA tile, BK=128, 2-stage ----------------
__global__ __launch_bounds__(512, 1) void hmma_gemm_bf16x3(
    const __nv_bfloat16* __restrict__ Ah, const __nv_bfloat16* __restrict__ Al,
    const __nv_bfloat16* __restrict__ Bh, const __nv_bfloat16* __restrict__ Bl,
    const float* __restrict__ bias, float* __restrict__ C, int ldc)
{
    extern __shared__ char dynsm[];

    const int tid = threadIdx.x;
    const int wid = tid >> 5;
    const int lane = tid & 31;
    const int g  = lane >> 2;
    const int tg = lane & 3;
    const int wm = wid >> 2;              // 0..3 -> 64-row slab
    const int wn = wid & 3;               // 0..3 -> 32-col slab
    const int m0 = blockIdx.y * GM;
    const int n0 = blockIdx.x * GN;

    const uint32_t s0 = smem_u32(dynsm);

    const int lq = lane >> 3, lr = lane & 7;
    const uint32_t a_off = (uint32_t)((wm * 64 + (lq & 1) * 8 + lr) * (SMST * 2) + (lq >> 1) * 16);
    const uint32_t b_off = (uint32_t)((wn * 32 + (lq >> 1) * 8 + lr) * (SMST * 2) + (lq & 1) * 16);

    float acc[4][4][4];
#pragma unroll
    for (int i = 0; i < 4; i++)
#pragma unroll
        for (int j = 0; j < 4; j++)
#pragma unroll
            for (int q = 0; q < 4; q++) acc[i][j][q] = 0.f;

    // per chunk: A 256 rows x 16 units of 16B + B 128 rows x 16 units = 6144 cp16 / 512 thr = 12
    auto issue_loads = [&](int c, int stg) {
        int s = c / CHPS, kc = (c - s * CHPS) * BK;
        const __nv_bfloat16* Ag = (s == 1) ? Al : Ah;
        const __nv_bfloat16* Bg = (s == 2) ? Bl : Bh;
        uint32_t base = s0 + (uint32_t)stg * STGB;
#pragma unroll
        for (int i = 0; i < 12; i++) {
            int idx = i * 512 + tid;           // 0..6143
            int r = idx >> 4, u = idx & 15;    // 16 x 16B per row
            if (r < GM)
                cp16(base + (uint32_t)(r * (SMST * 2) + u * 16),
                     (const char*)(Ag + (size_t)(m0 + r) * GK + kc) + u * 16);
            else
                cp16(base + ABUF + (uint32_t)((r - GM) * (SMST * 2) + u * 16),
                     (const char*)(Bg + (size_t)(n0 + r - GM) * GK + kc) + u * 16);
        }
    };

    issue_loads(0, 0);
    asm volatile("cp.async.commit_group;" ::: "memory");

    for (int c = 0; c < NCHUNK; c++) {
        const int buf = c & 1;
        if (c + 1 < NCHUNK) issue_loads(c + 1, buf ^ 1);
        asm volatile("cp.async.commit_group;" ::: "memory");
        asm volatile("cp.async.wait_group 1;" ::: "memory");
        __syncthreads();

        const uint32_t base = s0 + (uint32_t)buf * STGB;
        const uint32_t aB = base + a_off;
        const uint32_t bB = base + ABUF + b_off;
#pragma unroll
        for (int kk = 0; kk < 8; kk++) {
            uint32_t bf[4][2];
#pragma unroll
            for (int jj = 0; jj < 2; jj++) {
                uint32_t t0, t1, t2, t3;
                ldsm4(t0, t1, t2, t3, bB + (uint32_t)(jj * 16 * (SMST * 2) + kk * 32));
                bf[2 * jj][0] = t0;     bf[2 * jj][1] = t1;
                bf[2 * jj + 1][0] = t2; bf[2 * jj + 1][1] = t3;
            }
#pragma unroll
            for (int i = 0; i < 4; i++) {
                uint32_t a0, a1, a2, a3;
                ldsm4(a0, a1, a2, a3, aB + (uint32_t)(i * 16 * (SMST * 2) + kk * 32));
#pragma unroll
                for (int j = 0; j < 4; j++)
                    mma_bf16(acc[i][j], a0, a1, a2, a3, bf[j][0], bf[j][1]);
            }
        }
        __syncthreads();
    }

#pragma unroll
    for (int i = 0; i < 4; i++) {
        int r0 = m0 + wm * 64 + i * 16 + g;
#pragma unroll
        for (int j = 0; j < 4; j++) {
            int cc = n0 + wn * 32 + j * 8 + tg * 2;
            float bx = 0.f, by = 0.f;
            if (bias) { bx = bias[cc]; by = bias[cc + 1]; }
            float2 v0 = { acc[i][j][0] + bx, acc[i][j][1] + by };
            float2 v1 = { acc[i][j][2] + bx, acc[i][j][3] + by };
            *(float2*)(C + (size_t)r0 * ldc + cc)       = v0;
            *(float2*)(C + (size_t)(r0 + 8) * ldc + cc) = v1;
        }
    }
}

// ---------------- per-row symmetric int8 quant of q and k ----------------
__global__ __launch_bounds__(256) void quant_qk_kernel()
{
    int warp = threadIdx.x >> 5, lane = threadIdx.x & 31;
    int row = blockIdx.x * 8 + warp;
    int t  = row >> 16;
    int rr = row & 65535;
    int bh = rr >> 11;
    int n  = rr & 2047;
    int b = bh >> 4, h = bh & 15;
    const float* src = g_qkv + (size_t)(b * NTOK + n) * K3 + t * CDIM + h * HD;

    float x0 = src[lane];
    float x1 = src[lane + 32];
    float x2 = (lane < 8) ? src[lane + 64] : 0.f;
    float amax = fmaxf(fabsf(x0), fmaxf(fabsf(x1), fabsf(x2)));
#pragma unroll
    for (int s = 16; s; s >>= 1) amax = fmaxf(amax, __shfl_xor_sync(0xffffffffu, amax, s));
    float scale = fmaxf(amax, 1e-8f) / 127.0f;

    signed char* dst = (t ? g_k8 : g_q8) + (size_t)(bh * NTOK + n) * QK_PAD;
    int q0 = min(127, max(-128, (int)rintf(__fdiv_rn(x0, scale))));
    int q1 = min(127, max(-128, (int)rintf(__fdiv_rn(x1, scale))));
    dst[lane]      = (signed char)q0;
    dst[lane + 32] = (signed char)q1;
    if (lane < 8) {
        int q2 = min(127, max(-128, (int)rintf(__fdiv_rn(x2, scale))));
        dst[lane + 64] = (signed char)q2;
    } else {
        dst[lane + 64] = 0;
    }
    if (lane == 0) (t ? g_ks : g_qs)[bh * NTOK + n] = scale;
}

// ---------------- v quant: clear / amax / quantize+transpose ----------------
__global__ __launch_bounds__(256) void vamax_clear_kernel()
{
    int i = blockIdx.x * 256 + threadIdx.x;
    if (i < BH * HD) g_vamax[i] = 0;
}

__global__ __launch_bounds__(256) void vamax_kernel()
{
    int bh = blockIdx.y, chunk = blockIdx.x;
    int b = bh >> 4, h = bh & 15;
    __shared__ int sm[HD];
    if (threadIdx.x < HD) sm[threadIdx.x] = 0;
    __syncthreads();

    const float* base = g_qkv + (size_t)b * NTOK * K3 + 2 * CDIM + h * HD;
    for (int idx = threadIdx.x; idx < 256 * HD; idx += 256) {
        int n = chunk * 256 + idx / HD;
        int d = idx % HD;
        float v = fabsf(base[(size_t)n * K3 + d]);
        atomicMax(&sm[d], __float_as_int(v));
    }
    __syncthreads();
    if (threadIdx.x < HD)
        atomicMax(&g_vamax[bh * HD + threadIdx.x], sm[threadIdx.x]);
}

#define VQ_SST 264
__global__ __launch_bounds__(256) void vquant_kernel()
{
    int bh = blockIdx.y, chunk = blockIdx.x;
    int b = bh >> 4, h = bh & 15;
    __shared__ char tile[HD * VQ_SST];
    __shared__ float scS[HD];
    if (threadIdx.x < HD) {
        float amax = __int_as_float(g_vamax[bh * HD + threadIdx.x]);
        float sc = fmaxf(amax, 1e-8f) / 127.0f;
        scS[threadIdx.x] = sc;
        if (chunk == 0) g_vs[bh * HD + threadIdx.x] = sc;
    }
    __syncthreads();

    const float* base = g_qkv + (size_t)b * NTOK * K3 + 2 * CDIM + h * HD;
    for (int idx = threadIdx.x; idx < 256 * HD; idx += 256) {
        int nl = idx / HD;
        int d  = idx % HD;
        float v = base[(size_t)(chunk * 256 + nl) * K3 + d];
        int q = min(127, max(-128, (int)rintf(__fdiv_rn(v, scS[d]))));
        tile[d * VQ_SST + nl] = (char)q;
    }
    __syncthreads();

    for (int idx = threadIdx.x; idx < HD * 64; idx += 256) {
        int d = idx >> 6, w = idx & 63;
        int val = *(const int*)&tile[d * VQ_SST + w * 4];
        *(int*)(g_v8 + (size_t)(bh * HD + d) * NTOK + chunk * 256 + w * 4) = val;
    }
}

// ---------------- int8 QK^T logits GEMM (IMMA m16n8k32), 128x128 tile ----------------
__global__ __launch_bounds__(256) void logits_kernel()
{
    int bh   = blockIdx.z;
    int row0 = blockIdx.y * 128;
    int col0 = blockIdx.x * 128;
    __shared__ char qS[128 * QK_SST];
    __shared__ char kS[128 * QK_SST];

    const int tid = threadIdx.x;
    const char* qg = (const char*)(g_q8 + (size_t)(bh * NTOK + row0) * QK_PAD);
    const char* kg = (const char*)(g_k8 + (size_t)(bh * NTOK + col0) * QK_PAD);
#pragma unroll
    for (int it = 0; it < 3; it++) {
        int idx = tid + it * 256;
        int rr = idx / 6, u = idx % 6;
        *(uint4*)(qS + rr * QK_SST + u * 16) = *(const uint4*)(qg + rr * QK_PAD + u * 16);
        *(uint4*)(kS + rr * QK_SST + u * 16) = *(const uint4*)(kg + rr * QK_PAD + u * 16);
    }
    __syncthreads();

    const int wid = tid >> 5, lane = tid & 31;
    const int lg = lane >> 2, lt = lane & 3;
    const int wm = wid >> 2, wn = wid & 3;

    const uint32_t sq = smem_u32(qS);
    const uint32_t sk = smem_u32(kS);
    const uint32_t aBase = sq + (uint32_t)((wm * 64 + lg) * QK_SST + lt * 4);
    const uint32_t bBase = sk + (uint32_t)((wn * 32 + lg) * QK_SST + lt * 4);

    int acc[4][4][4] = {};
#pragma unroll
    for (int k = 0; k < 3; k++) {
        uint32_t bf[4][2];
#pragma unroll
        for (int j = 0; j < 4; j++) {
            uint32_t ba = bBase + (uint32_t)(j * 8 * QK_SST + k * 32);
            bf[j][0] = lds32(ba);
            bf[j][1] = lds32(ba + 16);
        }
#pragma unroll
        for (int i = 0; i < 4; i++) {
            uint32_t aa = aBase + (uint32_t)(i * 16 * QK_SST + k * 32);
            uint32_t a0 = lds32(aa);
            uint32_t a1 = lds32(aa + 8 * QK_SST);
            uint32_t a2 = lds32(aa + 16);
            uint32_t a3 = lds32(aa + 8 * QK_SST + 16);
#pragma unroll
            for (int j = 0; j < 4; j++)
                mma_s8(acc[i][j], a0, a1, a2, a3, bf[j][0], bf[j][1]);
        }
    }

#pragma unroll
    for (int i = 0; i < 4; i++) {
        int r0 = row0 + wm * 64 + i * 16 + lg;
        float qs0 = g_qs[bh * NTOK + r0] * ATT_SCALE;
        float qs1 = g_qs[bh * NTOK + r0 + 8] * ATT_SCALE;
#pragma unroll
        for (int j = 0; j < 4; j++) {
            int cc = col0 + wn * 32 + j * 8 + lt * 2;
            float2 kk = *(const float2*)&g_ks[bh * NTOK + cc];
            float2 v0 = { (float)acc[i][j][0] * qs0 * kk.x, (float)acc[i][j][1] * qs0 * kk.y };
            float2 v1 = { (float)acc[i][j][2] * qs1 * kk.x, (float)acc[i][j][3] * qs1 * kk.y };
            *(float2*)(g_logits + ((size_t)bh * NTOK + r0) * NTOK + cc)       = v0;
            *(float2*)(g_logits + ((size_t)bh * NTOK + r0 + 8) * NTOK + cc)   = v1;
        }
    }
}

// ---------------- softmax + u8 quant: 256 thr x 8 elems, __expf, shuffle reduce ----------------
__global__ __launch_bounds__(256) void softmax_kernel()
{
    size_t rowbase = (size_t)blockIdx.x * NTOK;
    const float* lrow = g_logits + rowbase;
    int tid = threadIdx.x;
    int wid = tid >> 5, lane = tid & 31;
    __shared__ float red[8];

    float4 l0 = *(const float4*)(lrow + tid * 8);
    float4 l1 = *(const float4*)(lrow + tid * 8 + 4);
    float m = fmaxf(fmaxf(fmaxf(l0.x, l0.y), fmaxf(l0.z, l0.w)),
                    fmaxf(fmaxf(l1.x, l1.y), fmaxf(l1.z, l1.w)));
#pragma unroll
    for (int s = 16; s; s >>= 1) m = fmaxf(m, __shfl_xor_sync(0xffffffffu, m, s));
    if (lane == 0) red[wid] = m;
    __syncthreads();
    m = fmaxf(fmaxf(fmaxf(red[0], red[1]), fmaxf(red[2], red[3])),
              fmaxf(fmaxf(red[4], red[5]), fmaxf(red[6], red[7])));

    float e[8];
    e[0] = __expf(l0.x - m); e[1] = __expf(l0.y - m);
    e[2] = __expf(l0.z - m); e[3] = __expf(l0.w - m);
    e[4] = __expf(l1.x - m); e[5] = __expf(l1.y - m);
    e[6] = __expf(l1.z - m); e[7] = __expf(l1.w - m);
    float z = ((e[0] + e[1]) + (e[2] + e[3])) + ((e[4] + e[5]) + (e[6] + e[7]));
#pragma unroll
    for (int s = 16; s; s >>= 1) z += __shfl_xor_sync(0xffffffffu, z, s);
    __syncthreads();           // red[] reuse
    if (lane == 0) red[wid] = z;
    __syncthreads();
    z = ((red[0] + red[1]) + (red[2] + red[3])) + ((red[4] + red[5]) + (red[6] + red[7]));

    unsigned pk0 = 0, pk1 = 0;
#pragma unroll
    for (int i = 0; i < 4; i++) {
        int p = min(255, max(0, (int)rintf(255.0f * e[i])));
        pk0 |= (unsigned)p << (8 * i);
    }
#pragma unroll
    for (int i = 0; i < 4; i++) {
        int p = min(255, max(0, (int)rintf(255.0f * e[4 + i])));
        pk1 |= (unsigned)p << (8 * i);
    }
    *(uint2*)(g_p8 + rowbase + tid * 8) = make_uint2(pk0, pk1);
    if (tid == 0) g_rowfac[blockIdx.x] = __fdiv_rn(1.0f, z) / 255.0f;
}

// ---------------- PV GEMM (IMMA u8.s8): ctx in split bf16 ----------------
#define PV_SST 48
__global__ __launch_bounds__(256, 2) void pv_kernel()
{
    int bh = blockIdx.y;
    int b = bh >> 4, h = bh & 15;
    int row0 = blockIdx.x * 256;

    __shared__ char pS[2][256 * PV_SST];
    __shared__ char vS[2][72 * PV_SST];

    const char* pg = (const char*)(g_p8 + ((size_t)bh * NTOK + row0) * NTOK);
    const char* vg = (const char*)(g_v8 + (size_t)bh * HD * NTOK);

    const int tid = threadIdx.x;
    const int wid = tid >> 5, lane = tid & 31;
    const int lg = lane >> 2, lt = lane & 3;
    const uint32_t sp0 = smem_u32(pS);
    const uint32_t sv0 = smem_u32(vS);

    auto issue = [&](int kc, int buf) {
        const char* srcp = pg + (size_t)tid * NTOK + kc * 32;
        uint32_t dstp = sp0 + (uint32_t)(buf * 256 * PV_SST + tid * PV_SST);
        cp16(dstp, srcp);
        cp16(dstp + 16, srcp + 16);
        if (tid < 144) {
            int rr = tid >> 1, u = tid & 1;
            cp16(sv0 + (uint32_t)(buf * 72 * PV_SST + rr * PV_SST + u * 16),
                 vg + (size_t)rr * NTOK + kc * 32 + u * 16);
        }
    };

    int acc[2][9][4] = {};

    issue(0, 0);
    asm volatile("cp.async.commit_group;" ::: "memory");

    for (int kc = 0; kc < 64; kc++) {
        const int buf = kc & 1;
        if (kc + 1 < 64) issue(kc + 1, buf ^ 1);
        asm volatile("cp.async.commit_group;" ::: "memory");
        asm volatile("cp.async.wait_group 1;" ::: "memory");
        __syncthreads();

        const uint32_t ap = sp0 + (uint32_t)(buf * 256 * PV_SST + (wid * 32 + lg) * PV_SST + lt * 4);
        const uint32_t bp = sv0 + (uint32_t)(buf * 72 * PV_SST + lg * PV_SST + lt * 4);

        uint32_t bf[9][2];
#pragma unroll
        for (int j = 0; j < 9; j++) {
            uint32_t ba = bp + (uint32_t)(j * 8 * PV_SST);
            bf[j][0] = lds32(ba);
            bf[j][1] = lds32(ba + 16);
        }
#pragma unroll
        for (int i = 0; i < 2; i++) {
            uint32_t aa = ap + (uint32_t)(i * 16 * PV_SST);
            uint32_t a0 = lds32(aa);
            uint32_t a1 = lds32(aa + 8 * PV_SST);
            uint32_t a2 = lds32(aa + 16);
            uint32_t a3 = lds32(aa + 8 * PV_SST + 16);
#pragma unroll
            for (int j = 0; j < 9; j++)
                mma_u8s8(acc[i][j], a0, a1, a2, a3, bf[j][0], bf[j][1]);
        }
        __syncthreads();
    }

#pragma unroll
    for (int i = 0; i < 2; i++) {
        int n0 = row0 + wid * 32 + i * 16 + lg;
        float rf0 = g_rowfac[bh * NTOK + n0];
        float rf1 = g_rowfac[bh * NTOK + n0 + 8];
#pragma unroll
        for (int j = 0; j < 9; j++) {
            int d = j * 8 + lt * 2;
            float vs0 = g_vs[bh * HD + d];
            float vs1 = g_vs[bh * HD + d + 1];
            float v00 = (float)acc[i][j][0] * rf0 * vs0;
            float v01 = (float)acc[i][j][1] * rf0 * vs1;
            float v10 = (float)acc[i][j][2] * rf1 * vs0;
            float v11 = (float)acc[i][j][3] * rf1 * vs1;
            size_t i0 = (size_t)(b * NTOK + n0) * CDIM + h * HD + d;
            size_t i1 = (size_t)(b * NTOK + n0 + 8) * CDIM + h * HD + d;
            __nv_bfloat16 h00 = __float2bfloat16_rn(v00);
            __nv_bfloat16 h01 = __float2bfloat16_rn(v01);
            __nv_bfloat16 h10 = __float2bfloat16_rn(v10);
            __nv_bfloat16 h11 = __float2bfloat16_rn(v11);
            *(__nv_bfloat162*)&g_ctx_hi[i0] = __nv_bfloat162(h00, h01);
            *(__nv_bfloat162*)&g_ctx_hi[i1] = __nv_bfloat162(h10, h11);
            *(__nv_bfloat162*)&g_ctx_lo[i0] = __nv_bfloat162(
                __float2bfloat16_rn(v00 - __bfloat162float(h00)),
                __float2bfloat16_rn(v01 - __bfloat162float(h01)));
            *(__nv_bfloat162*)&g_ctx_lo[i1] = __nv_bfloat162(
                __float2bfloat16_rn(v10 - __bfloat162float(h10)),
                __float2bfloat16_rn(v11 - __bfloat162float(h11)));
        }
    }
}

// ---------------- launch ----------------
extern "C" void kernel_launch(void* const* d_in, const int* in_sizes, int n_in,
                              void* d_out, int out_size)
{
    const float* x      = (const float*)d_in[0];
    const float* w_qkv  = (const float*)d_in[1];
    const float* w_proj = (const float*)d_in[2];
    const float* b_proj = (const float*)d_in[3];
    float* out = (float*)d_out;
    (void)in_sizes; (void)n_in; (void)out_size;

    void *p_qkv = nullptr;
    void *p_xh = nullptr, *p_xl = nullptr, *p_wqh = nullptr, *p_wql = nullptr;
    void *p_wph = nullptr, *p_wpl = nullptr, *p_cxh = nullptr, *p_cxl = nullptr;
    cudaGetSymbolAddress(&p_qkv, g_qkv);
    cudaGetSymbolAddress(&p_xh, g_x_hi);   cudaGetSymbolAddress(&p_xl, g_x_lo);
    cudaGetSymbolAddress(&p_wqh, g_wq_hi); cudaGetSymbolAddress(&p_wql, g_wq_lo);
    cudaGetSymbolAddress(&p_wph, g_wp_hi); cudaGetSymbolAddress(&p_wpl, g_wp_lo);
    cudaGetSymbolAddress(&p_cxh, g_ctx_hi); cudaGetSymbolAddress(&p_cxl, g_ctx_lo);

    cudaFuncSetAttribute(hmma_gemm_bf16x3, cudaFuncAttributeMaxDynamicSharedMemorySize, GEMM_SMEM);

    // 0) split fp32 operands into bf16 hi/lo
    {
        int nx = MROWS * CDIM, nq = K3 * CDIM, np = CDIM * CDIM;
        split_kernel<<<(nx + 255) / 256, 256>>>(x, (__nv_bfloat16*)p_xh, (__nv_bfloat16*)p_xl, nx);
        split_kernel<<<(nq + 255) / 256, 256>>>(w_qkv, (__nv_bfloat16*)p_wqh, (__nv_bfloat16*)p_wql, nq);
        split_kernel<<<(np + 255) / 256, 256>>>(w_proj, (__nv_bfloat16*)p_wph, (__nv_bfloat16*)p_wpl, np);
    }

    // 1) QKV projection (HMMA bf16x3), 256x128 tiles, BK=128
    hmma_gemm_bf16x3<<<dim3(K3 / GN, MROWS / GM), 512, GEMM_SMEM>>>(
        (const __nv_bfloat16*)p_xh, (const __nv_bfloat16*)p_xl,
        (const __nv_bfloat16*)p_wqh, (const __nv_bfloat16*)p_wql,
        nullptr, (float*)p_qkv, K3);

    // 2) quantize q,k per row; v per channel
    quant_qk_kernel<<<2 * BH * NTOK / 8, 256>>>();
    vamax_clear_kernel<<<(BH * HD + 255) / 256, 256>>>();
    vamax_kernel<<<dim3(NTOK / 256, BH), 256>>>();
    vquant_kernel<<<dim3(NTOK / 256, BH), 256>>>();

    // 3) int8 logits GEMM (IMMA)
    logits_kernel<<<dim3(NTOK / 128, NTOK / 128, BH), 256>>>();

    // 4) softmax + u8 quant
    softmax_kernel<<<BH * NTOK, 256>>>();

    // 5) PV GEMM (IMMA) -> ctx (split bf16)
    pv_kernel<<<dim3(NTOK / 256, BH), 256>>>();

    // 6) output projection + bias (HMMA bf16x3)
    hmma_gemm_bf16x3<<<dim3(CDIM / GN, MROWS / GM), 512, GEMM_SMEM>>>(
        (const __nv_bfloat16*)p_cxh, (const __nv_bfloat16*)p_cxl,
        (const __nv_bfloat16*)p_wph, (const __nv_bfloat16*)p_wpl,
        b_proj, out, CDIM);
}

// round 12
// speedup vs baseline: 1.1642x; 1.0824x over previous
#include <cuda_runtime.h>
#include <cuda_bf16.h>
#include <cstdint>
#include <cstddef>

#define BATCH 2
#define NTOK 2048
#define CDIM 1152
#define HEADS 16
#define HD 72
#define BH (BATCH*HEADS)      /* 32   */
#define MROWS (BATCH*NTOK)    /* 4096 */
#define K3 (3*CDIM)           /* 3456 */
#define QK_PAD 96
#define QK_SST 112
#define ATT_SCALE 0.11785113019775793f  /* 72^-0.5 */

#define GK CDIM
#define BK 64                 /* K per smem chunk (bf16 elems) */
#define CHPS (GK/BK)          /* 18 */
#define NCHUNK (3*CHPS)       /* 54 */
#define SMST 72               /* smem row stride in bf16 (144 B = 128 data + 16 skew) */
#define GS 4
#define GM 256                /* CTA tile rows */
#define GN 128                /* CTA tile cols */
#define ABUF (GM*SMST*2)      /* 36864 */
#define BBUF (GN*SMST*2)      /* 18432 */
#define STGB (ABUF+BBUF)      /* 55296 */
#define GEMM_SMEM (GS*STGB)   /* 221184 */

// ---------------- scratch (static device memory) ----------------
__device__ float g_qkv[(size_t)MROWS * K3];
__device__ __align__(16) signed char g_q8[(size_t)BH * NTOK * QK_PAD];
__device__ __align__(16) signed char g_k8[(size_t)BH * NTOK * QK_PAD];
__device__ float g_qs[BH * NTOK];
__device__ float g_ks[BH * NTOK];
__device__ __align__(16) signed char g_v8[(size_t)BH * HD * NTOK];   // [bh][d][m]
__device__ float g_vs[BH * HD];
__device__ int   g_vamax[BH * HD];
__device__ float g_logits[(size_t)BH * NTOK * NTOK];
__device__ __align__(16) unsigned char g_p8[(size_t)BH * NTOK * NTOK];
__device__ float g_rowfac[BH * NTOK];

// bf16 split operands
__device__ __align__(16) __nv_bfloat16 g_x_hi[(size_t)MROWS * CDIM];
__device__ __align__(16) __nv_bfloat16 g_x_lo[(size_t)MROWS * CDIM];
__device__ __align__(16) __nv_bfloat16 g_wq_hi[(size_t)K3 * CDIM];
__device__ __align__(16) __nv_bfloat16 g_wq_lo[(size_t)K3 * CDIM];
__device__ __align__(16) __nv_bfloat16 g_wp_hi[(size_t)CDIM * CDIM];
__device__ __align__(16) __nv_bfloat16 g_wp_lo[(size_t)CDIM * CDIM];
__device__ __align__(16) __nv_bfloat16 g_ctx_hi[(size_t)MROWS * CDIM];
__device__ __align__(16) __nv_bfloat16 g_ctx_lo[(size_t)MROWS * CDIM];

// ---------------- helpers ----------------
__device__ __forceinline__ uint32_t smem_u32(const void* p) {
    uint32_t a;
    asm("{ .reg .u64 t; cvta.to.shared.u64 t, %1; cvt.u32.u64 %0, t; }" : "=r"(a) : "l"(p));
    return a;
}
__device__ __forceinline__ uint32_t lds32(uint32_t addr) {
    uint32_t v;
    asm volatile("ld.shared.b32 %0, [%1];" : "=r"(v) : "r"(addr));
    return v;
}
__device__ __forceinline__ void mma_bf16(float* c, uint32_t a0, uint32_t a1,
                                         uint32_t a2, uint32_t a3,
                                         uint32_t b0, uint32_t b1) {
    asm volatile(
        "mma.sync.aligned.m16n8k16.row.col.f32.bf16.bf16.f32 "
        "{%0,%1,%2,%3}, {%4,%5,%6,%7}, {%8,%9}, {%0,%1,%2,%3};"
        : "+f"(c[0]), "+f"(c[1]), "+f"(c[2]), "+f"(c[3])
        : "r"(a0), "r"(a1), "r"(a2), "r"(a3), "r"(b0), "r"(b1));
}
__device__ __forceinline__ void mma_s8(int* c, uint32_t a0, uint32_t a1,
                                       uint32_t a2, uint32_t a3,
                                       uint32_t b0, uint32_t b1) {
    asm volatile(
        "mma.sync.aligned.m16n8k32.row.col.s32.s8.s8.s32 "
        "{%0,%1,%2,%3}, {%4,%5,%6,%7}, {%8,%9}, {%0,%1,%2,%3};"
        : "+r"(c[0]), "+r"(c[1]), "+r"(c[2]), "+r"(c[3])
        : "r"(a0), "r"(a1), "r"(a2), "r"(a3), "r"(b0), "r"(b1));
}
__device__ __forceinline__ void mma_u8s8(int* c, uint32_t a0, uint32_t a1,
                                         uint32_t a2, uint32_t a3,
                                         uint32_t b0, uint32_t b1) {
    asm volatile(
        "mma.sync.aligned.m16n8k32.row.col.s32.u8.s8.s32 "
        "{%0,%1,%2,%3}, {%4,%5,%6,%7}, {%8,%9}, {%0,%1,%2,%3};"
        : "+r"(c[0]), "+r"(c[1]), "+r"(c[2]), "+r"(c[3])
        : "r"(a0), "r"(a1), "r"(a2), "r"(a3), "r"(b0), "r"(b1));
}
__device__ __forceinline__ void ldsm4(uint32_t& r0, uint32_t& r1, uint32_t& r2,
                                      uint32_t& r3, uint32_t addr) {
    asm volatile("ldmatrix.sync.aligned.m8n8.x4.shared.b16 {%0,%1,%2,%3}, [%4];"
                 : "=r"(r0), "=r"(r1), "=r"(r2), "=r"(r3) : "r"(addr));
}
__device__ __forceinline__ void cp16(uint32_t dst, const void* src) {
    asm volatile("cp.async.cg.shared.global [%0], [%1], 16;" :: "r"(dst), "l"(src));
}

// ---------------- split fp32 -> bf16 hi + lo ----------------
__global__ __launch_bounds__(256) void split_kernel(const float* __restrict__ s,
                                                    __nv_bfloat16* __restrict__ hi,
                                                    __nv_bfloat16* __restrict__ lo, int n)
{
    int i = blockIdx.x * 256 + threadIdx.x;
    if (i < n) {
        float v = s[i];
        __nv_bfloat16 h = __float2bfloat16_rn(v);
        hi[i] = h;
        lo[i] = __float2bfloat16_rn(v - __bfloat162float(h));
    }
}

// ---------------- HMMA bf16x3 GEMM: 256x128 CTA tile, BK=64, GS=4 (R10 measured best) ----------------
__global__ __launch_bounds__(512, 1) void hmma_gemm_bf16x3(
    const __nv_bfloat16* __restrict__ Ah, const __nv_bfloat16* __restrict__ Al,
    const __nv_bfloat16* __restrict__ Bh, const __nv_bfloat16* __restrict__ Bl,
    const float* __restrict__ bias, float* __restrict__ C, int ldc)
{
    extern __shared__ char dynsm[];

    const int tid = threadIdx.x;
    const int wid = tid >> 5;
    const int lane = tid & 31;
    const int g  = lane >> 2;
    const int tg = lane & 3;
    const int wm = wid >> 2;              // 0..3 -> 64-row slab
    const int wn = wid & 3;               // 0..3 -> 32-col slab
    const int m0 = blockIdx.y * GM;
    const int n0 = blockIdx.x * GN;

    const uint32_t s0 = smem_u32(dynsm);

    const int lq = lane >> 3, lr = lane & 7;
    const uint32_t a_off = (uint32_t)((wm * 64 + (lq & 1) * 8 + lr) * (SMST * 2) + (lq >> 1) * 16);
    const uint32_t b_off = (uint32_t)((wn * 32 + (lq >> 1) * 8 + lr) * (SMST * 2) + (lq & 1) * 16);

    float acc[4][4][4];
#pragma unroll
    for (int i = 0; i < 4; i++)
#pragma unroll
        for (int j = 0; j < 4; j++)
#pragma unroll
            for (int q = 0; q < 4; q++) acc[i][j][q] = 0.f;

    // per chunk: A 256 rows x 8 units of 16B, B 128 rows x 8 units -> 3072 cp16 / 512 thr = 6
    auto issue_loads = [&](int c, int stg) {
        int s = c / CHPS, kc = (c - s * CHPS) * BK;
        const __nv_bfloat16* Ag = (s == 1) ? Al : Ah;
        const __nv_bfloat16* Bg = (s == 2) ? Bl : Bh;
        uint32_t base = s0 + (uint32_t)stg * STGB;
#pragma unroll
        for (int i = 0; i < 6; i++) {
            int idx = i * 512 + tid;           // 0..3071
            int r = idx >> 3, u = idx & 7;     // 8 x 16B per row
            if (r < GM)
                cp16(base + (uint32_t)(r * (SMST * 2) + u * 16),
                     (const char*)(Ag + (size_t)(m0 + r) * GK + kc) + u * 16);
            else
                cp16(base + ABUF + (uint32_t)((r - GM) * (SMST * 2) + u * 16),
                     (const char*)(Bg + (size_t)(n0 + r - GM) * GK + kc) + u * 16);
        }
    };

#pragma unroll
    for (int s = 0; s < GS - 1; s++) {
        issue_loads(s, s);
        asm volatile("cp.async.commit_group;" ::: "memory");
    }

    for (int c = 0; c < NCHUNK; c++) {
        asm volatile("cp.async.wait_group %0;" :: "n"(GS - 2) : "memory");
        __syncthreads();
        if (c + GS - 1 < NCHUNK) issue_loads(c + GS - 1, (c + GS - 1) % GS);
        asm volatile("cp.async.commit_group;" ::: "memory");

        const uint32_t base = s0 + (uint32_t)(c % GS) * STGB;
        const uint32_t aB = base + a_off;
        const uint32_t bB = base + ABUF + b_off;
#pragma unroll
        for (int kk = 0; kk < 4; kk++) {
            uint32_t bf[4][2];
#pragma unroll
            for (int jj = 0; jj < 2; jj++) {
                uint32_t t0, t1, t2, t3;
                ldsm4(t0, t1, t2, t3, bB + (uint32_t)(jj * 16 * (SMST * 2) + kk * 32));
                bf[2 * jj][0] = t0;     bf[2 * jj][1] = t1;
                bf[2 * jj + 1][0] = t2; bf[2 * jj + 1][1] = t3;
            }
#pragma unroll
            for (int i = 0; i < 4; i++) {
                uint32_t a0, a1, a2, a3;
                ldsm4(a0, a1, a2, a3, aB + (uint32_t)(i * 16 * (SMST * 2) + kk * 32));
#pragma unroll
                for (int j = 0; j < 4; j++)
                    mma_bf16(acc[i][j], a0, a1, a2, a3, bf[j][0], bf[j][1]);
            }
        }
    }

#pragma unroll
    for (int i = 0; i < 4; i++) {
        int r0 = m0 + wm * 64 + i * 16 + g;
#pragma unroll
        for (int j = 0; j < 4; j++) {
            int cc = n0 + wn * 32 + j * 8 + tg * 2;
            float bx = 0.f, by = 0.f;
            if (bias) { bx = bias[cc]; by = bias[cc + 1]; }
            float2 v0 = { acc[i][j][0] + bx, acc[i][j][1] + by };
            float2 v1 = { acc[i][j][2] + bx, acc[i][j][3] + by };
            *(float2*)(C + (size_t)r0 * ldc + cc)       = v0;
            *(float2*)(C + (size_t)(r0 + 8) * ldc + cc) = v1;
        }
    }
}

// ---------------- per-row symmetric int8 quant of q and k ----------------
__global__ __launch_bounds__(256) void quant_qk_kernel()
{
    int warp = threadIdx.x >> 5, lane = threadIdx.x & 31;
    int row = blockIdx.x * 8 + warp;
    int t  = row >> 16;
    int rr = row & 65535;
    int bh = rr >> 11;
    int n  = rr & 2047;
    int b = bh >> 4, h = bh & 15;
    const float* src = g_qkv + (size_t)(b * NTOK + n) * K3 + t * CDIM + h * HD;

    float x0 = src[lane];
    float x1 = src[lane + 32];
    float x2 = (lane < 8) ? src[lane + 64] : 0.f;
    float amax = fmaxf(fabsf(x0), fmaxf(fabsf(x1), fabsf(x2)));
#pragma unroll
    for (int s = 16; s; s >>= 1) amax = fmaxf(amax, __shfl_xor_sync(0xffffffffu, amax, s));
    float scale = fmaxf(amax, 1e-8f) / 127.0f;

    signed char* dst = (t ? g_k8 : g_q8) + (size_t)(bh * NTOK + n) * QK_PAD;
    int q0 = min(127, max(-128, (int)rintf(__fdiv_rn(x0, scale))));
    int q1 = min(127, max(-128, (int)rintf(__fdiv_rn(x1, scale))));
    dst[lane]      = (signed char)q0;
    dst[lane + 32] = (signed char)q1;
    if (lane < 8) {
        int q2 = min(127, max(-128, (int)rintf(__fdiv_rn(x2, scale))));
        dst[lane + 64] = (signed char)q2;
    } else {
        dst[lane + 64] = 0;
    }
    if (lane == 0) (t ? g_ks : g_qs)[bh * NTOK + n] = scale;
}

// ---------------- v quant: clear / amax / quantize+transpose ----------------
__global__ __launch_bounds__(256) void vamax_clear_kernel()
{
    int i = blockIdx.x * 256 + threadIdx.x;
    if (i < BH * HD) g_vamax[i] = 0;
}

__global__ __launch_bounds__(256) void vamax_kernel()
{
    int bh = blockIdx.y, chunk = blockIdx.x;
    int b = bh >> 4, h = bh & 15;
    __shared__ int sm[HD];
    if (threadIdx.x < HD) sm[threadIdx.x] = 0;
    __syncthreads();

    const float* base = g_qkv + (size_t)b * NTOK * K3 + 2 * CDIM + h * HD;
    for (int idx = threadIdx.x; idx < 256 * HD; idx += 256) {
        int n = chunk * 256 + idx / HD;
        int d = idx % HD;
        float v = fabsf(base[(size_t)n * K3 + d]);
        atomicMax(&sm[d], __float_as_int(v));
    }
    __syncthreads();
    if (threadIdx.x < HD)
        atomicMax(&g_vamax[bh * HD + threadIdx.x], sm[threadIdx.x]);
}

#define VQ_SST 264
__global__ __launch_bounds__(256) void vquant_kernel()
{
    int bh = blockIdx.y, chunk = blockIdx.x;
    int b = bh >> 4, h = bh & 15;
    __shared__ char tile[HD * VQ_SST];
    __shared__ float scS[HD];
    if (threadIdx.x < HD) {
        float amax = __int_as_float(g_vamax[bh * HD + threadIdx.x]);
        float sc = fmaxf(amax, 1e-8f) / 127.0f;
        scS[threadIdx.x] = sc;
        if (chunk == 0) g_vs[bh * HD + threadIdx.x] = sc;
    }
    __syncthreads();

    const float* base = g_qkv + (size_t)b * NTOK * K3 + 2 * CDIM + h * HD;
    for (int idx = threadIdx.x; idx < 256 * HD; idx += 256) {
        int nl = idx / HD;
        int d  = idx % HD;
        float v = base[(size_t)(chunk * 256 + nl) * K3 + d];
        int q = min(127, max(-128, (int)rintf(__fdiv_rn(v, scS[d]))));
        tile[d * VQ_SST + nl] = (char)q;
    }
    __syncthreads();

    for (int idx = threadIdx.x; idx < HD * 64; idx += 256) {
        int d = idx >> 6, w = idx & 63;
        int val = *(const int*)&tile[d * VQ_SST + w * 4];
        *(int*)(g_v8 + (size_t)(bh * HD + d) * NTOK + chunk * 256 + w * 4) = val;
    }
}

// ---------------- int8 QK^T logits GEMM (IMMA m16n8k32), 128x128 tile ----------------
__global__ __launch_bounds__(256) void logits_kernel()
{
    int bh   = blockIdx.z;
    int row0 = blockIdx.y * 128;
    int col0 = blockIdx.x * 128;
    __shared__ char qS[128 * QK_SST];
    __shared__ char kS[128 * QK_SST];

    const int tid = threadIdx.x;
    const char* qg = (const char*)(g_q8 + (size_t)(bh * NTOK + row0) * QK_PAD);
    const char* kg = (const char*)(g_k8 + (size_t)(bh * NTOK + col0) * QK_PAD);
#pragma unroll
    for (int it = 0; it < 3; it++) {
        int idx = tid + it * 256;
        int rr = idx / 6, u = idx % 6;
        *(uint4*)(qS + rr * QK_SST + u * 16) = *(const uint4*)(qg + rr * QK_PAD + u * 16);
        *(uint4*)(kS + rr * QK_SST + u * 16) = *(const uint4*)(kg + rr * QK_PAD + u * 16);
    }
    __syncthreads();

    const int wid = tid >> 5, lane = tid & 31;
    const int lg = lane >> 2, lt = lane & 3;
    const int wm = wid >> 2, wn = wid & 3;

    const uint32_t sq = smem_u32(qS);
    const uint32_t sk = smem_u32(kS);
    const uint32_t aBase = sq + (uint32_t)((wm * 64 + lg) * QK_SST + lt * 4);
    const uint32_t bBase = sk + (uint32_t)((wn * 32 + lg) * QK_SST + lt * 4);

    int acc[4][4][4] = {};
#pragma unroll
    for (int k = 0; k < 3; k++) {
        uint32_t bf[4][2];
#pragma unroll
        for (int j = 0; j < 4; j++) {
            uint32_t ba = bBase + (uint32_t)(j * 8 * QK_SST + k * 32);
            bf[j][0] = lds32(ba);
            bf[j][1] = lds32(ba + 16);
        }
#pragma unroll
        for (int i = 0; i < 4; i++) {
            uint32_t aa = aBase + (uint32_t)(i * 16 * QK_SST + k * 32);
            uint32_t a0 = lds32(aa);
            uint32_t a1 = lds32(aa + 8 * QK_SST);
            uint32_t a2 = lds32(aa + 16);
            uint32_t a3 = lds32(aa + 8 * QK_SST + 16);
#pragma unroll
            for (int j = 0; j < 4; j++)
                mma_s8(acc[i][j], a0, a1, a2, a3, bf[j][0], bf[j][1]);
        }
    }

#pragma unroll
    for (int i = 0; i < 4; i++) {
        int r0 = row0 + wm * 64 + i * 16 + lg;
        float qs0 = g_qs[bh * NTOK + r0] * ATT_SCALE;
        float qs1 = g_qs[bh * NTOK + r0 + 8] * ATT_SCALE;
#pragma unroll
        for (int j = 0; j < 4; j++) {
            int cc = col0 + wn * 32 + j * 8 + lt * 2;
            float2 kk = *(const float2*)&g_ks[bh * NTOK + cc];
            float2 v0 = { (float)acc[i][j][0] * qs0 * kk.x, (float)acc[i][j][1] * qs0 * kk.y };
            float2 v1 = { (float)acc[i][j][2] * qs1 * kk.x, (float)acc[i][j][3] * qs1 * kk.y };
            *(float2*)(g_logits + ((size_t)bh * NTOK + r0) * NTOK + cc)       = v0;
            *(float2*)(g_logits + ((size_t)bh * NTOK + r0 + 8) * NTOK + cc)   = v1;
        }
    }
}

// ---------------- softmax + u8 quant: 256 thr x 8 elems, __expf, shuffle reduce ----------------
__global__ __launch_bounds__(256) void softmax_kernel()
{
    size_t rowbase = (size_t)blockIdx.x * NTOK;
    const float* lrow = g_logits + rowbase;
    int tid = threadIdx.x;
    int wid = tid >> 5, lane = tid & 31;
    __shared__ float red[8];

    float4 l0 = *(const float4*)(lrow + tid * 8);
    float4 l1 = *(const float4*)(lrow + tid * 8 + 4);
    float m = fmaxf(fmaxf(fmaxf(l0.x, l0.y), fmaxf(l0.z, l0.w)),
                    fmaxf(fmaxf(l1.x, l1.y), fmaxf(l1.z, l1.w)));
#pragma unroll
    for (int s = 16; s; s >>= 1) m = fmaxf(m, __shfl_xor_sync(0xffffffffu, m, s));
    if (lane == 0) red[wid] = m;
    __syncthreads();
    m = fmaxf(fmaxf(fmaxf(red[0], red[1]), fmaxf(red[2], red[3])),
              fmaxf(fmaxf(red[4], red[5]), fmaxf(red[6], red[7])));

    float e[8];
    e[0] = __expf(l0.x - m); e[1] = __expf(l0.y - m);
    e[2] = __expf(l0.z - m); e[3] = __expf(l0.w - m);
    e[4] = __expf(l1.x - m); e[5] = __expf(l1.y - m);
    e[6] = __expf(l1.z - m); e[7] = __expf(l1.w - m);
    float z = ((e[0] + e[1]) + (e[2] + e[3])) + ((e[4] + e[5]) + (e[6] + e[7]));
#pragma unroll
    for (int s = 16; s; s >>= 1) z += __shfl_xor_sync(0xffffffffu, z, s);
    __syncthreads();           // red[] reuse
    if (lane == 0) red[wid] = z;
    __syncthreads();
    z = ((red[0] + red[1]) + (red[2] + red[3])) + ((red[4] + red[5]) + (red[6] + red[7]));

    unsigned pk0 = 0, pk1 = 0;
#pragma unroll
    for (int i = 0; i < 4; i++) {
        int p = min(255, max(0, (int)rintf(255.0f * e[i])));
        pk0 |= (unsigned)p << (8 * i);
    }
#pragma unroll
    for (int i = 0; i < 4; i++) {
        int p = min(255, max(0, (int)rintf(255.0f * e[4 + i])));
        pk1 |= (unsigned)p << (8 * i);
    }
    *(uint2*)(g_p8 + rowbase + tid * 8) = make_uint2(pk0, pk1);
    if (tid == 0) g_rowfac[blockIdx.x] = __fdiv_rn(1.0f, z) / 255.0f;
}

// ---------------- PV GEMM (IMMA u8.s8): ctx in split bf16 ----------------
#define PV_SST 48
__global__ __launch_bounds__(256, 2) void pv_kernel()
{
    int bh = blockIdx.y;
    int b = bh >> 4, h = bh & 15;
    int row0 = blockIdx.x * 256;

    __shared__ char pS[2][256 * PV_SST];
    __shared__ char vS[2][72 * PV_SST];

    const char* pg = (const char*)(g_p8 + ((size_t)bh * NTOK + row0) * NTOK);
    const char* vg = (const char*)(g_v8 + (size_t)bh * HD * NTOK);

    const int tid = threadIdx.x;
    const int wid = tid >> 5, lane = tid & 31;
    const int lg = lane >> 2, lt = lane & 3;
    const uint32_t sp0 = smem_u32(pS);
    const uint32_t sv0 = smem_u32(vS);

    auto issue = [&](int kc, int buf) {
        const char* srcp = pg + (size_t)tid * NTOK + kc * 32;
        uint32_t dstp = sp0 + (uint32_t)(buf * 256 * PV_SST + tid * PV_SST);
        cp16(dstp, srcp);
        cp16(dstp + 16, srcp + 16);
        if (tid < 144) {
            int rr = tid >> 1, u = tid & 1;
            cp16(sv0 + (uint32_t)(buf * 72 * PV_SST + rr * PV_SST + u * 16),
                 vg + (size_t)rr * NTOK + kc * 32 + u * 16);
        }
    };

    int acc[2][9][4] = {};

    issue(0, 0);
    asm volatile("cp.async.commit_group;" ::: "memory");

    for (int kc = 0; kc < 64; kc++) {
        const int buf = kc & 1;
        if (kc + 1 < 64) issue(kc + 1, buf ^ 1);
        asm volatile("cp.async.commit_group;" ::: "memory");
        asm volatile("cp.async.wait_group 1;" ::: "memory");
        __syncthreads();

        const uint32_t ap = sp0 + (uint32_t)(buf * 256 * PV_SST + (wid * 32 + lg) * PV_SST + lt * 4);
        const uint32_t bp = sv0 + (uint32_t)(buf * 72 * PV_SST + lg * PV_SST + lt * 4);

        uint32_t bf[9][2];
#pragma unroll
        for (int j = 0; j < 9; j++) {
            uint32_t ba = bp + (uint32_t)(j * 8 * PV_SST);
            bf[j][0] = lds32(ba);
            bf[j][1] = lds32(ba + 16);
        }
#pragma unroll
        for (int i = 0; i < 2; i++) {
            uint32_t aa = ap + (uint32_t)(i * 16 * PV_SST);
            uint32_t a0 = lds32(aa);
            uint32_t a1 = lds32(aa + 8 * PV_SST);
            uint32_t a2 = lds32(aa + 16);
            uint32_t a3 = lds32(aa + 8 * PV_SST + 16);
#pragma unroll
            for (int j = 0; j < 9; j++)
                mma_u8s8(acc[i][j], a0, a1, a2, a3, bf[j][0], bf[j][1]);
        }
        __syncthreads();
    }

#pragma unroll
    for (int i = 0; i < 2; i++) {
        int n0 = row0 + wid * 32 + i * 16 + lg;
        float rf0 = g_rowfac[bh * NTOK + n0];
        float rf1 = g_rowfac[bh * NTOK + n0 + 8];
#pragma unroll
        for (int j = 0; j < 9; j++) {
            int d = j * 8 + lt * 2;
            float vs0 = g_vs[bh * HD + d];
            float vs1 = g_vs[bh * HD + d + 1];
            float v00 = (float)acc[i][j][0] * rf0 * vs0;
            float v01 = (float)acc[i][j][1] * rf0 * vs1;
            float v10 = (float)acc[i][j][2] * rf1 * vs0;
            float v11 = (float)acc[i][j][3] * rf1 * vs1;
            size_t i0 = (size_t)(b * NTOK + n0) * CDIM + h * HD + d;
            size_t i1 = (size_t)(b * NTOK + n0 + 8) * CDIM + h * HD + d;
            __nv_bfloat16 h00 = __float2bfloat16_rn(v00);
            __nv_bfloat16 h01 = __float2bfloat16_rn(v01);
            __nv_bfloat16 h10 = __float2bfloat16_rn(v10);
            __nv_bfloat16 h11 = __float2bfloat16_rn(v11);
            *(__nv_bfloat162*)&g_ctx_hi[i0] = __nv_bfloat162(h00, h01);
            *(__nv_bfloat162*)&g_ctx_hi[i1] = __nv_bfloat162(h10, h11);
            *(__nv_bfloat162*)&g_ctx_lo[i0] = __nv_bfloat162(
                __float2bfloat16_rn(v00 - __bfloat162float(h00)),
                __float2bfloat16_rn(v01 - __bfloat162float(h01)));
            *(__nv_bfloat162*)&g_ctx_lo[i1] = __nv_bfloat162(
                __float2bfloat16_rn(v10 - __bfloat162float(h10)),
                __float2bfloat16_rn(v11 - __bfloat162float(h11)));
        }
    }
}

// ---------------- launch ----------------
extern "C" void kernel_launch(void* const* d_in, const int* in_sizes, int n_in,
                              void* d_out, int out_size)
{
    const float* x      = (const float*)d_in[0];
    const float* w_qkv  = (const float*)d_in[1];
    const float* w_proj = (const float*)d_in[2];
    const float* b_proj = (const float*)d_in[3];
    float* out = (float*)d_out;
    (void)in_sizes; (void)n_in; (void)out_size;

    void *p_qkv = nullptr;
    void *p_xh = nullptr, *p_xl = nullptr, *p_wqh = nullptr, *p_wql = nullptr;
    void *p_wph = nullptr, *p_wpl = nullptr, *p_cxh = nullptr, *p_cxl = nullptr;
    cudaGetSymbolAddress(&p_qkv, g_qkv);
    cudaGetSymbolAddress(&p_xh, g_x_hi);   cudaGetSymbolAddress(&p_xl, g_x_lo);
    cudaGetSymbolAddress(&p_wqh, g_wq_hi); cudaGetSymbolAddress(&p_wql, g_wq_lo);
    cudaGetSymbolAddress(&p_wph, g_wp_hi); cudaGetSymbolAddress(&p_wpl, g_wp_lo);
    cudaGetSymbolAddress(&p_cxh, g_ctx_hi); cudaGetSymbolAddress(&p_cxl, g_ctx_lo);

    cudaFuncSetAttribute(hmma_gemm_bf16x3, cudaFuncAttributeMaxDynamicSharedMemorySize, GEMM_SMEM);

    // 0) split fp32 operands into bf16 hi/lo
    {
        int nx = MROWS * CDIM, nq = K3 * CDIM, np = CDIM * CDIM;
        split_kernel<<<(nx + 255) / 256, 256>>>(x, (__nv_bfloat16*)p_xh, (__nv_bfloat16*)p_xl, nx);
        split_kernel<<<(nq + 255) / 256, 256>>>(w_qkv, (__nv_bfloat16*)p_wqh, (__nv_bfloat16*)p_wql, nq);
        split_kernel<<<(np + 255) / 256, 256>>>(w_proj, (__nv_bfloat16*)p_wph, (__nv_bfloat16*)p_wpl, np);
    }

    // 1) QKV projection (HMMA bf16x3), 256x128 tiles, BK=64, GS=4
    hmma_gemm_bf16x3<<<dim3(K3 / GN, MROWS / GM), 512, GEMM_SMEM>>>(
        (const __nv_bfloat16*)p_xh, (const __nv_bfloat16*)p_xl,
        (const __nv_bfloat16*)p_wqh, (const __nv_bfloat16*)p_wql,
        nullptr, (float*)p_qkv, K3);

    // 2) quantize q,k per row; v per channel
    quant_qk_kernel<<<2 * BH * NTOK / 8, 256>>>();
    vamax_clear_kernel<<<(BH * HD + 255) / 256, 256>>>();
    vamax_kernel<<<dim3(NTOK / 256, BH), 256>>>();
    vquant_kernel<<<dim3(NTOK / 256, BH), 256>>>();

    // 3) int8 logits GEMM (IMMA)
    logits_kernel<<<dim3(NTOK / 128, NTOK / 128, BH), 256>>>();

    // 4) softmax + u8 quant
    softmax_kernel<<<BH * NTOK, 256>>>();

    // 5) PV GEMM (IMMA) -> ctx (split bf16)
    pv_kernel<<<dim3(NTOK / 256, BH), 256>>>();

    // 6) output projection + bias (HMMA bf16x3)
    hmma_gemm_bf16x3<<<dim3(CDIM / GN, MROWS / GM), 512, GEMM_SMEM>>>(
        (const __nv_bfloat16*)p_cxh, (const __nv_bfloat16*)p_cxl,
        (const __nv_bfloat16*)p_wph, (const __nv_bfloat16*)p_wpl,
        b_proj, out, CDIM);
}